// round 9
// baseline (speedup 1.0000x reference)
#include <cuda_runtime.h>
#include <math.h>

#define B_ 512
#define N_ 128
#define E_ 256
#define H_ 8
#define D_ 32
#define SCALE_ 0.17677669529663687f  /* 1/sqrt(32) */
#define NEGV  (-1000000000.0f)
#define CLIPV 10.0f
#define MTU   129                    /* Ms4T row stride in float4 units */

// ---------------- scratch (device globals; no allocation) ----------------
__device__ float g_qkv[(size_t)B_ * N_ * 768];   // k | v | logit_k
__device__ float g_Qc [(size_t)B_ * N_ * E_];    // X @ Wstep_bot
__device__ float g_M  [(size_t)B_ * N_ * E_];    // logit_k @ Wmlp^T
__device__ float g_P  [(size_t)B_ * N_ * 1024];  // precomputed attn logits [b][i][h][n]
__device__ float g_vt [(size_t)B_ * E_ * N_];    // v transposed [b][d][n]
__device__ float g_bdot[B_ * N_];
__device__ float g_ge [B_ * E_];
__device__ float g_qf [B_ * E_];

// ---------------- graph_emb = mean over nodes ----------------
__global__ void mean_k(const float* __restrict__ ne) {
    int b = blockIdx.x, e = threadIdx.x;
    const float* p = ne + (size_t)b * N_ * E_ + e;
    float s = 0.f;
#pragma unroll 8
    for (int n = 0; n < N_; n++) s += p[(size_t)n * E_];
    g_ge[b * E_ + e] = s * (1.0f / N_);
}

// ---------------- q_first = ge@Wfix + first@Wstep_top + bfix + bstep ----------------
__global__ void qfirst_k(const float* __restrict__ ne,
                         const float* __restrict__ Wfix, const float* __restrict__ bfix,
                         const float* __restrict__ Wstep, const float* __restrict__ bstep) {
    __shared__ float ge_s[E_], fi_s[E_];
    int b = blockIdx.x, t = threadIdx.x;
    ge_s[t] = g_ge[b * E_ + t];
    fi_s[t] = ne[(size_t)b * N_ * E_ + t];
    __syncthreads();
    float acc = bfix[t] + bstep[t];
#pragma unroll 4
    for (int f = 0; f < E_; f++) {
        acc = fmaf(ge_s[f], Wfix[f * E_ + t], acc);
        acc = fmaf(fi_s[f], Wstep[f * E_ + t], acc);
    }
    g_qf[b * E_ + t] = acc;
}

// ---------------- generic fp32 GEMM: C = A(MxK)*B(KxN) [+bias] ----------------
template <int TRANSB>
__global__ void __launch_bounds__(256) sgemm_k(
    const float* __restrict__ A, const float* __restrict__ Bm,
    const float* __restrict__ bias, float* __restrict__ C,
    int K, int lda, int ldb, int ldc) {
    __shared__ float As[8][128];
    __shared__ float Bs[8][128];
    int tid = threadIdx.x;
    int tx = tid & 15, ty = tid >> 4;
    int rowBase = blockIdx.y * 128;
    int colBase = blockIdx.x * 128;

    float acc[8][8];
#pragma unroll
    for (int i = 0; i < 8; i++)
#pragma unroll
        for (int j = 0; j < 8; j++) acc[i][j] = 0.f;

    int aR = tid >> 1;
    int aC = (tid & 1) * 4;
    int bK_n = tid >> 5;
    int bC_n = (tid & 31) * 4;
    int bCol_t = tid & 127;
    int bK_t = (tid >> 7) * 4;

    for (int kt = 0; kt < K; kt += 8) {
        float4 av = *(const float4*)(A + (size_t)(rowBase + aR) * lda + kt + aC);
        As[aC + 0][aR] = av.x; As[aC + 1][aR] = av.y;
        As[aC + 2][aR] = av.z; As[aC + 3][aR] = av.w;
        if (!TRANSB) {
            float4 bv = *(const float4*)(Bm + (size_t)(kt + bK_n) * ldb + colBase + bC_n);
            *(float4*)&Bs[bK_n][bC_n] = bv;
        } else {
            float4 bv = *(const float4*)(Bm + (size_t)(colBase + bCol_t) * ldb + kt + bK_t);
            Bs[bK_t + 0][bCol_t] = bv.x; Bs[bK_t + 1][bCol_t] = bv.y;
            Bs[bK_t + 2][bCol_t] = bv.z; Bs[bK_t + 3][bCol_t] = bv.w;
        }
        __syncthreads();
#pragma unroll
        for (int kk = 0; kk < 8; kk++) {
            float ra[8], rb[8];
            *(float4*)&ra[0] = *(const float4*)&As[kk][ty * 8];
            *(float4*)&ra[4] = *(const float4*)&As[kk][ty * 8 + 4];
            *(float4*)&rb[0] = *(const float4*)&Bs[kk][tx * 8];
            *(float4*)&rb[4] = *(const float4*)&Bs[kk][tx * 8 + 4];
#pragma unroll
            for (int i = 0; i < 8; i++)
#pragma unroll
                for (int j = 0; j < 8; j++) acc[i][j] = fmaf(ra[i], rb[j], acc[i][j]);
        }
        __syncthreads();
    }
#pragma unroll
    for (int i = 0; i < 8; i++) {
        int r = rowBase + ty * 8 + i;
#pragma unroll
        for (int j = 0; j < 8; j += 4) {
            int c = colBase + tx * 8 + j;
            float4 v;
            v.x = acc[i][j]; v.y = acc[i][j + 1]; v.z = acc[i][j + 2]; v.w = acc[i][j + 3];
            if (bias) { v.x += bias[c]; v.y += bias[c + 1]; v.z += bias[c + 2]; v.w += bias[c + 3]; }
            *(float4*)(C + (size_t)r * ldc + c) = v;
        }
    }
}

// ---------------- P[b][i][h][n] = SCALE * (qf[b]+Qc[b][i])_h . k[b][n]_h ----------------
__global__ void __launch_bounds__(256) pmat_k(float* __restrict__ P) {
    __shared__ float kt[32][132];
    __shared__ float qt[32][132];
    int h = blockIdx.x & 7, b = blockIdx.x >> 3;
    int tid = threadIdx.x;
    const float* kb  = g_qkv + (size_t)b * N_ * 768 + h * 32;
    const float* qcb = g_Qc  + (size_t)b * N_ * 256 + h * 32;
    const float* qfb = g_qf  + b * 256 + h * 32;

    for (int idx = tid; idx < N_ * 8; idx += 256) {
        int n = idx >> 3, d4 = (idx & 7) * 4;
        float4 kv  = *(const float4*)(kb  + (size_t)n * 768 + d4);
        float4 qv  = *(const float4*)(qcb + (size_t)n * 256 + d4);
        float4 qf4 = *(const float4*)(qfb + d4);
        kt[d4 + 0][n] = kv.x; kt[d4 + 1][n] = kv.y;
        kt[d4 + 2][n] = kv.z; kt[d4 + 3][n] = kv.w;
        qt[d4 + 0][n] = qv.x + qf4.x; qt[d4 + 1][n] = qv.y + qf4.y;
        qt[d4 + 2][n] = qv.z + qf4.z; qt[d4 + 3][n] = qv.w + qf4.w;
    }
    __syncthreads();

    int tx = tid & 15, ty = tid >> 4;
    float acc[8][8];
#pragma unroll
    for (int i = 0; i < 8; i++)
#pragma unroll
        for (int j = 0; j < 8; j++) acc[i][j] = 0.f;

#pragma unroll 4
    for (int d = 0; d < 32; d++) {
        float ra[8], rb[8];
        *(float4*)&ra[0] = *(const float4*)&qt[d][ty * 8];
        *(float4*)&ra[4] = *(const float4*)&qt[d][ty * 8 + 4];
        *(float4*)&rb[0] = *(const float4*)&kt[d][tx * 8];
        *(float4*)&rb[4] = *(const float4*)&kt[d][tx * 8 + 4];
#pragma unroll
        for (int i = 0; i < 8; i++)
#pragma unroll
            for (int j = 0; j < 8; j++) acc[i][j] = fmaf(ra[i], rb[j], acc[i][j]);
    }

#pragma unroll
    for (int i = 0; i < 8; i++) {
        float* row = P + ((size_t)(b * N_ + ty * 8 + i)) * 1024 + h * 128 + tx * 8;
#pragma unroll
        for (int j = 0; j < 8; j += 4) {
            float4 v;
            v.x = acc[i][j] * SCALE_;     v.y = acc[i][j + 1] * SCALE_;
            v.z = acc[i][j + 2] * SCALE_; v.w = acc[i][j + 3] * SCALE_;
            *(float4*)(row + j) = v;
        }
    }
}

// ---------------- v transpose: g_vt[b][d][n] = qkv[b][n][256+d] ----------------
__global__ void __launch_bounds__(256) vtrans_k() {
    __shared__ float ts[32][33];
    int b = blockIdx.x >> 3, dt = blockIdx.x & 7;
    int tid = threadIdx.x;
    const float* src = g_qkv + (size_t)b * N_ * 768 + 256 + dt * 32;
    float* dst = g_vt + ((size_t)b * 256 + dt * 32) * 128;
    for (int nt = 0; nt < 4; nt++) {
        int nn = tid >> 3, dd4 = (tid & 7) * 4;
        float4 vv = *(const float4*)(src + (size_t)(nt * 32 + nn) * 768 + dd4);
        ts[dd4 + 0][nn] = vv.x; ts[dd4 + 1][nn] = vv.y;
        ts[dd4 + 2][nn] = vv.z; ts[dd4 + 3][nn] = vv.w;
        __syncthreads();
        int dd = tid >> 5, n2 = tid & 31;
#pragma unroll
        for (int r = 0; r < 4; r++)
            dst[(size_t)(dd + r * 8) * 128 + nt * 32 + n2] = ts[dd + r * 8][n2];
        __syncthreads();
    }
}

// ---------------- bdot[row] = SCALE * (bmlp . logit_k[row]) ----------------
__global__ void bdot_k(const float* __restrict__ bmlp) {
    int w = threadIdx.x >> 5, l = threadIdx.x & 31;
    int row = blockIdx.x * 8 + w;
    const float* lk = g_qkv + (size_t)row * 768 + 512;
    float acc = 0.f;
#pragma unroll
    for (int j = 0; j < 8; j++) acc = fmaf(bmlp[l + 32 * j], lk[l + 32 * j], acc);
#pragma unroll
    for (int o = 16; o; o >>= 1) acc += __shfl_xor_sync(0xffffffffu, acc, o);
    if (l == 0) g_bdot[row] = acc * SCALE_;
}

// ---------------- sequential greedy decode: 1 CTA (512 thr) per batch ----------------
// 3 barriers/step:
//  A (warps 0-7): softmax from preloaded P row -> attn_s            | bar1
//  B (all):       ctx via attn_s broadcast-LDS + v regs -> ctx_s     | bar2
//  CD (all):      M.ctx partial per (n,q) lane, shfl-reduce in-warp,
//                 lanes 0-7 store raw tanh logits -> logits_s        | bar3
//  E (all, redundant): mask via visD, top-2 argmax -> cur; warps 0-7
//                 immediately issue next P LDG; warp 8 prefetches the
//                 runner-up's row; then lse/logf behind the load.
__global__ void __launch_bounds__(512, 1) decode_k(float* __restrict__ out) {
    extern __shared__ float dyn_s[];
    float4* Ms4T = (float4*)dyn_s;                   // [64 u][MTU], n contiguous

    __shared__ float attn_s[H_ * 132];               // [h][n], +4 pad at n>=64
    __shared__ float ctx_s[E_];
    __shared__ float logits_s[N_];
    __shared__ float bd_s[N_];

    int b = blockIdx.x, tid = threadIdx.x;
    int w = tid >> 5, l = tid & 31;
    int qC = l >> 3, nlC = l & 7;                    // CD mapping
    int nC = 8 * w + nlC;

    const float4* Mb4 = (const float4*)(g_M + (size_t)b * N_ * E_);
    const float4* Pb = (const float4*)(g_P + (size_t)b * N_ * 1024);

    // ---- stage M transposed: Ms4T[u][n] = M[n][u] ----
    for (int idx = tid; idx < N_ * 64; idx += 512) {
        int n = idx >> 6, u = idx & 63;
        Ms4T[u * MTU + n] = Mb4[n * 64 + u];
    }
    // ---- stage v into regs: thread t holds v[nh*64+i][d], d=t>>1, nh=t&1 ----
    float v_reg[64];
    {
        int d = tid >> 1, nh = tid & 1;
        const float4* vb4 = (const float4*)(g_vt + ((size_t)b * 256 + d) * 128 + nh * 64);
#pragma unroll
        for (int i = 0; i < 16; i++) {
            float4 t = vb4[i];
            v_reg[4 * i + 0] = t.x; v_reg[4 * i + 1] = t.y;
            v_reg[4 * i + 2] = t.z; v_reg[4 * i + 3] = t.w;
        }
    }
    if (tid < N_) bd_s[tid] = g_bdot[b * N_ + tid];
    __syncthreads();

    // register state (redundant per thread)
    unsigned visA = (l == 0) ? 1u : 0u;              // bits 0..3 for n = 4l..4l+3
    unsigned visD = (l == 0) ? 1u : 0u;              // bit j for n = l + 32j
    float lp = 0.f;

    // prime: P row for cur = 0
    float4 pv;
    if (w < 8) pv = Pb[/*cur*/ 0 * 256 + w * 32 + l];

    for (int step = 0; step < N_ - 1; step++) {
        // ---- A: warps 0..7 = heads; lane l owns n = 4l..4l+3 ----
        if (w < 8) {
            int n0 = 4 * l;
            float a0 = (visA & 1u) ? NEGV : pv.x;
            float a1 = (visA & 2u) ? NEGV : pv.y;
            float a2 = (visA & 4u) ? NEGV : pv.z;
            float a3 = (visA & 8u) ? NEGV : pv.w;
            float m = fmaxf(fmaxf(a0, a1), fmaxf(a2, a3));
#pragma unroll
            for (int o = 16; o; o >>= 1) m = fmaxf(m, __shfl_xor_sync(0xffffffffu, m, o));
            a0 = expf(a0 - m); a1 = expf(a1 - m); a2 = expf(a2 - m); a3 = expf(a3 - m);
            float ssum = a0 + a1 + a2 + a3;
#pragma unroll
            for (int o = 16; o; o >>= 1) ssum += __shfl_xor_sync(0xffffffffu, ssum, o);
            float inv = 1.0f / ssum;
            float4 wv;
            wv.x = a0 * inv; wv.y = a1 * inv; wv.z = a2 * inv; wv.w = a3 * inv;
            *(float4*)&attn_s[w * 132 + n0 + 4 * (l >= 16)] = wv;
        }
        __syncthreads();

        // ---- B: ctx[d] = sum_n attn[h(d)][n] * v[n][d] ----
        {
            int d = tid >> 1, nh = tid & 1, hh = d >> 5;
            const float* ap = attn_s + hh * 132 + nh * 68;
            float acc0 = 0.f, acc1 = 0.f;
#pragma unroll
            for (int i = 0; i < 64; i += 2) {
                acc0 = fmaf(ap[i], v_reg[i], acc0);
                acc1 = fmaf(ap[i + 1], v_reg[i + 1], acc1);
            }
            float acc = acc0 + acc1;
            acc += __shfl_xor_sync(0xffffffffu, acc, 1);
            if (!nh) ctx_s[d] = acc;
        }
        __syncthreads();

        // ---- CD: lane (qC,nlC) partial-dots d-units [16qC,16qC+16) of row nC;
        //          in-warp shfl reduce over qC; lanes 0-7 store raw tanh logits ----
        {
            const float4* c4 = (const float4*)ctx_s + qC * 16;
            const float4* mr = Ms4T + (qC * 16) * MTU + nC;
            float s0 = 0.f, s1 = 0.f, s2 = 0.f, s3 = 0.f;
#pragma unroll
            for (int i = 0; i < 16; i++) {
                float4 mv = mr[i * MTU], c = c4[i];
                s0 = fmaf(c.x, mv.x, s0); s1 = fmaf(c.y, mv.y, s1);
                s2 = fmaf(c.z, mv.z, s2); s3 = fmaf(c.w, mv.w, s3);
            }
            float acc = (s0 + s1) + (s2 + s3);
            acc += __shfl_xor_sync(0xffffffffu, acc, 8);
            acc += __shfl_xor_sync(0xffffffffu, acc, 16);
            if (l < 8) {
                int n = 8 * w + l;
                logits_s[n] = tanhf(fmaf(SCALE_, acc, bd_s[n])) * CLIPV;
            }
        }
        __syncthreads();

        // ---- E: redundant on all warps. argmax FIRST, then load, then lse ----
        float lv[4];
        float v1 = -3.0e38f, v2 = -3.0e38f;
        int i1 = 0, i2 = 0;
#pragma unroll
        for (int j = 0; j < 4; j++) {
            int n = l + 32 * j;
            float lg = logits_s[n];
            if ((visD >> j) & 1u) lg = NEGV;
            lv[j] = lg;
            if (lg > v1) { v2 = v1; i2 = i1; v1 = lg; i1 = n; }
            else if (lg > v2) { v2 = lg; i2 = n; }
        }
#pragma unroll
        for (int o = 16; o; o >>= 1) {
            float ov1 = __shfl_xor_sync(0xffffffffu, v1, o);
            float ov2 = __shfl_xor_sync(0xffffffffu, v2, o);
            int oi1 = __shfl_xor_sync(0xffffffffu, i1, o);
            int oi2 = __shfl_xor_sync(0xffffffffu, i2, o);
            if (ov1 > v1 || (ov1 == v1 && oi1 < i1)) {
                if (v1 >= ov2) { v2 = v1; i2 = i1; }
                else { v2 = ov2; i2 = oi2; }
                v1 = ov1; i1 = oi1;
            } else {
                if (ov1 >= v2) { v2 = ov1; i2 = oi1; }
            }
        }
        int cur = i1;
        // state update (before issuing loads so A's masks are ready)
        if ((cur >> 2) == l) visA |= 1u << (cur & 3);
        if ((cur & 31) == l) visD |= 1u << (cur >> 5);

        // issue next P row load NOW (hides DRAM latency behind lse below)
        if (w < 8) pv = Pb[(size_t)cur * 256 + w * 32 + l];
        // warp 8: prefetch runner-up's row into L1 (speculation; free if wrong)
        if (w == 8) {
            const char* pp = (const char*)(Pb + (size_t)i2 * 256) + l * 128;
            asm volatile("prefetch.global.L1 [%0];" :: "l"(pp));
        }

        // lse + logp (runs while the P load is in flight)
        float es = 0.f;
#pragma unroll
        for (int j = 0; j < 4; j++) es += expf(lv[j] - v1);
#pragma unroll
        for (int o = 16; o; o >>= 1) es += __shfl_xor_sync(0xffffffffu, es, o);
        lp -= logf(es);
        // no trailing barrier: bar1..bar3 of the next step order all smem reuse
    }

    if (tid == 0) out[b] = lp;
}

// ---------------- host launch ----------------
extern "C" void kernel_launch(void* const* d_in, const int* in_sizes, int n_in,
                              void* d_out, int out_size) {
    const float* ne    = (const float*)d_in[0];
    const float* Wqkv  = (const float*)d_in[1];
    const float* bqkv  = (const float*)d_in[2];
    const float* Wfix  = (const float*)d_in[3];
    const float* bfix  = (const float*)d_in[4];
    const float* Wstep = (const float*)d_in[5];
    const float* bstep = (const float*)d_in[6];
    const float* Wmlp  = (const float*)d_in[7];
    const float* bmlp  = (const float*)d_in[8];
    float* out = (float*)d_out;

    float *p_qkv = nullptr, *p_Qc = nullptr, *p_M = nullptr, *p_P = nullptr;
    cudaGetSymbolAddress((void**)&p_qkv, g_qkv);
    cudaGetSymbolAddress((void**)&p_Qc, g_Qc);
    cudaGetSymbolAddress((void**)&p_M, g_M);
    cudaGetSymbolAddress((void**)&p_P, g_P);

    size_t dec_smem = (size_t)64 * MTU * sizeof(float4);   // 132096
    cudaFuncSetAttribute(decode_k, cudaFuncAttributeMaxDynamicSharedMemorySize,
                         (int)dec_smem);

    mean_k<<<B_, E_>>>(ne);
    qfirst_k<<<B_, E_>>>(ne, Wfix, bfix, Wstep, bstep);

    sgemm_k<0><<<dim3(768 / 128, (B_ * N_) / 128), 256>>>(ne, Wqkv, bqkv, p_qkv,
                                                          E_, E_, 768, 768);
    sgemm_k<0><<<dim3(E_ / 128, (B_ * N_) / 128), 256>>>(ne, Wstep + 256 * 256, nullptr,
                                                         p_Qc, E_, E_, E_, E_);
    sgemm_k<1><<<dim3(E_ / 128, (B_ * N_) / 128), 256>>>(p_qkv + 512, Wmlp, nullptr,
                                                         p_M, E_, 768, E_, E_);
    pmat_k<<<B_ * H_, 256>>>(p_P);
    vtrans_k<<<B_ * 8, 256>>>();
    bdot_k<<<(B_ * N_) / 8, 256>>>(bmlp);

    decode_k<<<B_, 512, dec_smem>>>(out);
}

// round 10
// speedup vs baseline: 1.1057x; 1.1057x over previous
#include <cuda_runtime.h>
#include <math.h>

#define B_ 512
#define N_ 128
#define E_ 256
#define H_ 8
#define D_ 32
#define SCALE_ 0.17677669529663687f  /* 1/sqrt(32) */
#define NEGV  (-1000000000.0f)
#define CLIPV 10.0f
#define MTU   129                    /* Ms4T row stride in float4 units */
#define MRC   6                      /* M float4s cached in registers per thread */

// ---------------- scratch (device globals; no allocation) ----------------
__device__ float g_qkv[(size_t)B_ * N_ * 768];   // k | v | logit_k
__device__ float g_Qc [(size_t)B_ * N_ * E_];    // X @ Wstep_bot
__device__ float g_M  [(size_t)B_ * N_ * E_];    // logit_k @ Wmlp^T
__device__ float g_P  [(size_t)B_ * N_ * 1024];  // precomputed attn logits [b][i][h][n]
__device__ float g_vt [(size_t)B_ * E_ * N_];    // v transposed [b][d][n]
__device__ float g_bdot[B_ * N_];
__device__ float g_ge [B_ * E_];
__device__ float g_qf [B_ * E_];

// ---------------- graph_emb = mean over nodes ----------------
__global__ void mean_k(const float* __restrict__ ne) {
    int b = blockIdx.x, e = threadIdx.x;
    const float* p = ne + (size_t)b * N_ * E_ + e;
    float s = 0.f;
#pragma unroll 8
    for (int n = 0; n < N_; n++) s += p[(size_t)n * E_];
    g_ge[b * E_ + e] = s * (1.0f / N_);
}

// ---------------- q_first = ge@Wfix + first@Wstep_top + bfix + bstep ----------------
__global__ void qfirst_k(const float* __restrict__ ne,
                         const float* __restrict__ Wfix, const float* __restrict__ bfix,
                         const float* __restrict__ Wstep, const float* __restrict__ bstep) {
    __shared__ float ge_s[E_], fi_s[E_];
    int b = blockIdx.x, t = threadIdx.x;
    ge_s[t] = g_ge[b * E_ + t];
    fi_s[t] = ne[(size_t)b * N_ * E_ + t];
    __syncthreads();
    float acc = bfix[t] + bstep[t];
#pragma unroll 4
    for (int f = 0; f < E_; f++) {
        acc = fmaf(ge_s[f], Wfix[f * E_ + t], acc);
        acc = fmaf(fi_s[f], Wstep[f * E_ + t], acc);
    }
    g_qf[b * E_ + t] = acc;
}

// ---------------- generic fp32 GEMM: C = A(MxK)*B(KxN) [+bias] ----------------
template <int TRANSB>
__global__ void __launch_bounds__(256) sgemm_k(
    const float* __restrict__ A, const float* __restrict__ Bm,
    const float* __restrict__ bias, float* __restrict__ C,
    int K, int lda, int ldb, int ldc) {
    __shared__ float As[8][128];
    __shared__ float Bs[8][128];
    int tid = threadIdx.x;
    int tx = tid & 15, ty = tid >> 4;
    int rowBase = blockIdx.y * 128;
    int colBase = blockIdx.x * 128;

    float acc[8][8];
#pragma unroll
    for (int i = 0; i < 8; i++)
#pragma unroll
        for (int j = 0; j < 8; j++) acc[i][j] = 0.f;

    int aR = tid >> 1;
    int aC = (tid & 1) * 4;
    int bK_n = tid >> 5;
    int bC_n = (tid & 31) * 4;
    int bCol_t = tid & 127;
    int bK_t = (tid >> 7) * 4;

    for (int kt = 0; kt < K; kt += 8) {
        float4 av = *(const float4*)(A + (size_t)(rowBase + aR) * lda + kt + aC);
        As[aC + 0][aR] = av.x; As[aC + 1][aR] = av.y;
        As[aC + 2][aR] = av.z; As[aC + 3][aR] = av.w;
        if (!TRANSB) {
            float4 bv = *(const float4*)(Bm + (size_t)(kt + bK_n) * ldb + colBase + bC_n);
            *(float4*)&Bs[bK_n][bC_n] = bv;
        } else {
            float4 bv = *(const float4*)(Bm + (size_t)(colBase + bCol_t) * ldb + kt + bK_t);
            Bs[bK_t + 0][bCol_t] = bv.x; Bs[bK_t + 1][bCol_t] = bv.y;
            Bs[bK_t + 2][bCol_t] = bv.z; Bs[bK_t + 3][bCol_t] = bv.w;
        }
        __syncthreads();
#pragma unroll
        for (int kk = 0; kk < 8; kk++) {
            float ra[8], rb[8];
            *(float4*)&ra[0] = *(const float4*)&As[kk][ty * 8];
            *(float4*)&ra[4] = *(const float4*)&As[kk][ty * 8 + 4];
            *(float4*)&rb[0] = *(const float4*)&Bs[kk][tx * 8];
            *(float4*)&rb[4] = *(const float4*)&Bs[kk][tx * 8 + 4];
#pragma unroll
            for (int i = 0; i < 8; i++)
#pragma unroll
                for (int j = 0; j < 8; j++) acc[i][j] = fmaf(ra[i], rb[j], acc[i][j]);
        }
        __syncthreads();
    }
#pragma unroll
    for (int i = 0; i < 8; i++) {
        int r = rowBase + ty * 8 + i;
#pragma unroll
        for (int j = 0; j < 8; j += 4) {
            int c = colBase + tx * 8 + j;
            float4 v;
            v.x = acc[i][j]; v.y = acc[i][j + 1]; v.z = acc[i][j + 2]; v.w = acc[i][j + 3];
            if (bias) { v.x += bias[c]; v.y += bias[c + 1]; v.z += bias[c + 2]; v.w += bias[c + 3]; }
            *(float4*)(C + (size_t)r * ldc + c) = v;
        }
    }
}

// ---------------- P[b][i][h][n] = SCALE * (qf[b]+Qc[b][i])_h . k[b][n]_h ----------------
__global__ void __launch_bounds__(256) pmat_k(float* __restrict__ P) {
    __shared__ float kt[32][132];
    __shared__ float qt[32][132];
    int h = blockIdx.x & 7, b = blockIdx.x >> 3;
    int tid = threadIdx.x;
    const float* kb  = g_qkv + (size_t)b * N_ * 768 + h * 32;
    const float* qcb = g_Qc  + (size_t)b * N_ * 256 + h * 32;
    const float* qfb = g_qf  + b * 256 + h * 32;

    for (int idx = tid; idx < N_ * 8; idx += 256) {
        int n = idx >> 3, d4 = (idx & 7) * 4;
        float4 kv  = *(const float4*)(kb  + (size_t)n * 768 + d4);
        float4 qv  = *(const float4*)(qcb + (size_t)n * 256 + d4);
        float4 qf4 = *(const float4*)(qfb + d4);
        kt[d4 + 0][n] = kv.x; kt[d4 + 1][n] = kv.y;
        kt[d4 + 2][n] = kv.z; kt[d4 + 3][n] = kv.w;
        qt[d4 + 0][n] = qv.x + qf4.x; qt[d4 + 1][n] = qv.y + qf4.y;
        qt[d4 + 2][n] = qv.z + qf4.z; qt[d4 + 3][n] = qv.w + qf4.w;
    }
    __syncthreads();

    int tx = tid & 15, ty = tid >> 4;
    float acc[8][8];
#pragma unroll
    for (int i = 0; i < 8; i++)
#pragma unroll
        for (int j = 0; j < 8; j++) acc[i][j] = 0.f;

#pragma unroll 4
    for (int d = 0; d < 32; d++) {
        float ra[8], rb[8];
        *(float4*)&ra[0] = *(const float4*)&qt[d][ty * 8];
        *(float4*)&ra[4] = *(const float4*)&qt[d][ty * 8 + 4];
        *(float4*)&rb[0] = *(const float4*)&kt[d][tx * 8];
        *(float4*)&rb[4] = *(const float4*)&kt[d][tx * 8 + 4];
#pragma unroll
        for (int i = 0; i < 8; i++)
#pragma unroll
            for (int j = 0; j < 8; j++) acc[i][j] = fmaf(ra[i], rb[j], acc[i][j]);
    }

#pragma unroll
    for (int i = 0; i < 8; i++) {
        float* row = P + ((size_t)(b * N_ + ty * 8 + i)) * 1024 + h * 128 + tx * 8;
#pragma unroll
        for (int j = 0; j < 8; j += 4) {
            float4 v;
            v.x = acc[i][j] * SCALE_;     v.y = acc[i][j + 1] * SCALE_;
            v.z = acc[i][j + 2] * SCALE_; v.w = acc[i][j + 3] * SCALE_;
            *(float4*)(row + j) = v;
        }
    }
}

// ---------------- v transpose: g_vt[b][d][n] = qkv[b][n][256+d] ----------------
__global__ void __launch_bounds__(256) vtrans_k() {
    __shared__ float ts[32][33];
    int b = blockIdx.x >> 3, dt = blockIdx.x & 7;
    int tid = threadIdx.x;
    const float* src = g_qkv + (size_t)b * N_ * 768 + 256 + dt * 32;
    float* dst = g_vt + ((size_t)b * 256 + dt * 32) * 128;
    for (int nt = 0; nt < 4; nt++) {
        int nn = tid >> 3, dd4 = (tid & 7) * 4;
        float4 vv = *(const float4*)(src + (size_t)(nt * 32 + nn) * 768 + dd4);
        ts[dd4 + 0][nn] = vv.x; ts[dd4 + 1][nn] = vv.y;
        ts[dd4 + 2][nn] = vv.z; ts[dd4 + 3][nn] = vv.w;
        __syncthreads();
        int dd = tid >> 5, n2 = tid & 31;
#pragma unroll
        for (int r = 0; r < 4; r++)
            dst[(size_t)(dd + r * 8) * 128 + nt * 32 + n2] = ts[dd + r * 8][n2];
        __syncthreads();
    }
}

// ---------------- bdot[row] = SCALE * (bmlp . logit_k[row]) ----------------
__global__ void bdot_k(const float* __restrict__ bmlp) {
    int w = threadIdx.x >> 5, l = threadIdx.x & 31;
    int row = blockIdx.x * 8 + w;
    const float* lk = g_qkv + (size_t)row * 768 + 512;
    float acc = 0.f;
#pragma unroll
    for (int j = 0; j < 8; j++) acc = fmaf(bmlp[l + 32 * j], lk[l + 32 * j], acc);
#pragma unroll
    for (int o = 16; o; o >>= 1) acc += __shfl_xor_sync(0xffffffffu, acc, o);
    if (l == 0) g_bdot[row] = acc * SCALE_;
}

// ---------------- sequential greedy decode: 1 CTA (512 thr) per batch ----------------
// R8 structure (4 barriers) with three cuts:
//  - C: 6/16 of each thread's M slice lives in registers -> 80KB smem/step
//  - B: attn read as float4 (16 LDS.128 broadcast vs 64 LDS)
//  - E: argmax -> state -> issue next P load -> lse behind the load
__global__ void __launch_bounds__(512, 1) decode_k(float* __restrict__ out) {
    extern __shared__ float dyn_s[];
    float4* Ms4T = (float4*)dyn_s;                   // [64 u][MTU], n contiguous

    __shared__ float attn_s[H_ * 132];               // [h][n], +4 pad at n>=64
    __shared__ float ctx_s[E_];
    __shared__ float lp_part[4][N_];
    __shared__ float logits_s[N_];
    __shared__ float bd_s[N_];

    int b = blockIdx.x, tid = threadIdx.x;
    int w = tid >> 5, l = tid & 31;
    int nL = tid & 127, pL = tid >> 7;

    const float4* Mb4 = (const float4*)(g_M + (size_t)b * N_ * E_);
    const float4* Pb = (const float4*)(g_P + (size_t)b * N_ * 1024);

    // ---- stage M transposed: Ms4T[u][n] = M[n][u] ----
    for (int idx = tid; idx < N_ * 64; idx += 512) {
        int n = idx >> 6, u = idx & 63;
        Ms4T[u * MTU + n] = Mb4[n * 64 + u];
    }
    // ---- register cache: first MRC float4 of this thread's M slice ----
    float4 Mreg[MRC];
#pragma unroll
    for (int i = 0; i < MRC; i++) Mreg[i] = Mb4[nL * 64 + pL * 16 + i];

    // ---- stage v into regs: thread t holds v[nh*64+i][d], d=t>>1, nh=t&1 ----
    float v_reg[64];
    {
        int d = tid >> 1, nh = tid & 1;
        const float4* vb4 = (const float4*)(g_vt + ((size_t)b * 256 + d) * 128 + nh * 64);
#pragma unroll
        for (int i = 0; i < 16; i++) {
            float4 t = vb4[i];
            v_reg[4 * i + 0] = t.x; v_reg[4 * i + 1] = t.y;
            v_reg[4 * i + 2] = t.z; v_reg[4 * i + 3] = t.w;
        }
    }
    if (tid < N_) bd_s[tid] = g_bdot[b * N_ + tid];
    __syncthreads();

    // register state (redundant per thread): cur implicit via loads; two vis maps
    unsigned visA = (l == 0) ? 1u : 0u;              // bits 0..3 for n = 4l..4l+3
    unsigned visD = (l == 0) ? 1u : 0u;              // bit j for n = l + 32j
    float lp = 0.f;

    // prime: P row for cur = 0
    float4 pv;
    if (w < 8) pv = Pb[0 * 256 + w * 32 + l];

    for (int step = 0; step < N_ - 1; step++) {
        // ---- A: warps 0..7 = heads; lane l owns n = 4l..4l+3 ----
        if (w < 8) {
            int n0 = 4 * l;
            float a0 = (visA & 1u) ? NEGV : pv.x;
            float a1 = (visA & 2u) ? NEGV : pv.y;
            float a2 = (visA & 4u) ? NEGV : pv.z;
            float a3 = (visA & 8u) ? NEGV : pv.w;
            float m = fmaxf(fmaxf(a0, a1), fmaxf(a2, a3));
#pragma unroll
            for (int o = 16; o; o >>= 1) m = fmaxf(m, __shfl_xor_sync(0xffffffffu, m, o));
            a0 = expf(a0 - m); a1 = expf(a1 - m); a2 = expf(a2 - m); a3 = expf(a3 - m);
            float ssum = a0 + a1 + a2 + a3;
#pragma unroll
            for (int o = 16; o; o >>= 1) ssum += __shfl_xor_sync(0xffffffffu, ssum, o);
            float inv = 1.0f / ssum;
            float4 wv;
            wv.x = a0 * inv; wv.y = a1 * inv; wv.z = a2 * inv; wv.w = a3 * inv;
            *(float4*)&attn_s[w * 132 + n0 + 4 * (l >= 16)] = wv;
        }
        __syncthreads();

        // ---- B: ctx[d] = sum_n attn[h(d)][n] * v[n][d]  (float4 broadcast LDS) ----
        {
            int d = tid >> 1, nh = tid & 1, hh = d >> 5;
            const float4* ap4 = (const float4*)(attn_s + hh * 132 + nh * 68);
            float acc0 = 0.f, acc1 = 0.f;
#pragma unroll
            for (int i = 0; i < 16; i++) {
                float4 av = ap4[i];
                acc0 = fmaf(av.x, v_reg[4 * i + 0], acc0);
                acc1 = fmaf(av.y, v_reg[4 * i + 1], acc1);
                acc0 = fmaf(av.z, v_reg[4 * i + 2], acc0);
                acc1 = fmaf(av.w, v_reg[4 * i + 3], acc1);
            }
            float acc = acc0 + acc1;
            acc += __shfl_xor_sync(0xffffffffu, acc, 1);
            if (!nh) ctx_s[d] = acc;
        }
        __syncthreads();

        // ---- C: logits partials; first MRC float4 from regs, rest from smem ----
        {
            const float4* c4 = (const float4*)ctx_s + pL * 16;
            const float4* mr = Ms4T + (pL * 16) * MTU + nL;
            float s0 = 0.f, s1 = 0.f, s2 = 0.f, s3 = 0.f;
#pragma unroll
            for (int i = 0; i < MRC; i++) {
                float4 mv = Mreg[i], c = c4[i];
                s0 = fmaf(c.x, mv.x, s0); s1 = fmaf(c.y, mv.y, s1);
                s2 = fmaf(c.z, mv.z, s2); s3 = fmaf(c.w, mv.w, s3);
            }
#pragma unroll
            for (int i = MRC; i < 16; i++) {
                float4 mv = mr[i * MTU], c = c4[i];
                s0 = fmaf(c.x, mv.x, s0); s1 = fmaf(c.y, mv.y, s1);
                s2 = fmaf(c.z, mv.z, s2); s3 = fmaf(c.w, mv.w, s3);
            }
            lp_part[pL][nL] = (s0 + s1) + (s2 + s3);
        }
        __syncthreads();

        // ---- D: tid<128 (n = tid): sum partials, one tanhf, mask -> logits_s ----
        if (tid < N_) {
            float s = lp_part[0][tid] + lp_part[1][tid] + lp_part[2][tid] + lp_part[3][tid];
            float lg = tanhf(fmaf(SCALE_, s, bd_s[tid])) * CLIPV;
            if ((visD >> w) & 1u) lg = NEGV;         // w<4, n = 32w + l, visD bit w
            logits_s[tid] = lg;
        }
        __syncthreads();

        // ---- E: argmax -> state -> issue next load -> lse behind the load ----
        {
            float lv[4];
            float bv = -3.0e38f; int bi = 0;
#pragma unroll
            for (int j = 0; j < 4; j++) {
                lv[j] = logits_s[l + 32 * j];
                if (lv[j] > bv) { bv = lv[j]; bi = l + 32 * j; }
            }
#pragma unroll
            for (int o = 16; o; o >>= 1) {
                float ov = __shfl_xor_sync(0xffffffffu, bv, o);
                int oi = __shfl_xor_sync(0xffffffffu, bi, o);
                if (ov > bv || (ov == bv && oi < bi)) { bv = ov; bi = oi; }
            }
            // state update + immediately issue next P row load
            if ((bi >> 2) == l) visA |= 1u << (bi & 3);
            if ((bi & 31) == l) visD |= 1u << (bi >> 5);
            if (w < 8) pv = Pb[(size_t)bi * 256 + w * 32 + l];

            // lse + logp while the load is in flight
            float es = 0.f;
#pragma unroll
            for (int j = 0; j < 4; j++) es += expf(lv[j] - bv);
#pragma unroll
            for (int o = 16; o; o >>= 1) es += __shfl_xor_sync(0xffffffffu, es, o);
            lp -= logf(es);
        }
        // no trailing barrier: bar1..bar4 of the next step order all smem reuse
    }

    if (tid == 0) out[b] = lp;
}

// ---------------- host launch ----------------
extern "C" void kernel_launch(void* const* d_in, const int* in_sizes, int n_in,
                              void* d_out, int out_size) {
    const float* ne    = (const float*)d_in[0];
    const float* Wqkv  = (const float*)d_in[1];
    const float* bqkv  = (const float*)d_in[2];
    const float* Wfix  = (const float*)d_in[3];
    const float* bfix  = (const float*)d_in[4];
    const float* Wstep = (const float*)d_in[5];
    const float* bstep = (const float*)d_in[6];
    const float* Wmlp  = (const float*)d_in[7];
    const float* bmlp  = (const float*)d_in[8];
    float* out = (float*)d_out;

    float *p_qkv = nullptr, *p_Qc = nullptr, *p_M = nullptr, *p_P = nullptr;
    cudaGetSymbolAddress((void**)&p_qkv, g_qkv);
    cudaGetSymbolAddress((void**)&p_Qc, g_Qc);
    cudaGetSymbolAddress((void**)&p_M, g_M);
    cudaGetSymbolAddress((void**)&p_P, g_P);

    size_t dec_smem = (size_t)64 * MTU * sizeof(float4);   // 132096
    cudaFuncSetAttribute(decode_k, cudaFuncAttributeMaxDynamicSharedMemorySize,
                         (int)dec_smem);

    mean_k<<<B_, E_>>>(ne);
    qfirst_k<<<B_, E_>>>(ne, Wfix, bfix, Wstep, bstep);

    sgemm_k<0><<<dim3(768 / 128, (B_ * N_) / 128), 256>>>(ne, Wqkv, bqkv, p_qkv,
                                                          E_, E_, 768, 768);
    sgemm_k<0><<<dim3(E_ / 128, (B_ * N_) / 128), 256>>>(ne, Wstep + 256 * 256, nullptr,
                                                         p_Qc, E_, E_, E_, E_);
    sgemm_k<1><<<dim3(E_ / 128, (B_ * N_) / 128), 256>>>(p_qkv + 512, Wmlp, nullptr,
                                                         p_M, E_, 768, E_, E_);
    pmat_k<<<B_ * H_, 256>>>(p_P);
    vtrans_k<<<B_ * 8, 256>>>();
    bdot_k<<<(B_ * N_) / 8, 256>>>(bmlp);

    decode_k<<<B_, 512, dec_smem>>>(out);
}

// round 11
// speedup vs baseline: 1.1256x; 1.0180x over previous
#include <cuda_runtime.h>
#include <math.h>

#define B_ 512
#define N_ 128
#define E_ 256
#define H_ 8
#define D_ 32
#define SCALE_ 0.17677669529663687f  /* 1/sqrt(32) */
#define NEGV  (-1000000000.0f)
#define CLIPV 10.0f
#define MTU   129                    /* Ms4T row stride in float4 units */
#define MRC   6                      /* M float4s cached in registers per thread */

typedef unsigned long long u64;

// packed fp32x2 FMA: d = a*b + d  (elementwise on (lo,hi))
__device__ __forceinline__ void ffma2(u64& d, u64 a, u64 b) {
    asm("fma.rn.f32x2 %0, %1, %2, %0;" : "+l"(d) : "l"(a), "l"(b));
}
__device__ __forceinline__ u64 pack2(float x, float y) {
    u64 r; asm("mov.b64 %0, {%1, %2};" : "=l"(r) : "f"(x), "f"(y)); return r;
}
__device__ __forceinline__ float2 unpack2(u64 v) {
    float2 r; asm("mov.b64 {%0, %1}, %2;" : "=f"(r.x), "=f"(r.y) : "l"(v)); return r;
}

// ---------------- scratch (device globals; no allocation) ----------------
__device__ float g_qkv[(size_t)B_ * N_ * 768];   // k | v | logit_k
__device__ float g_Qc [(size_t)B_ * N_ * E_];    // X @ Wstep_bot
__device__ float g_M  [(size_t)B_ * N_ * E_];    // logit_k @ Wmlp^T
__device__ float g_P  [(size_t)B_ * N_ * 1024];  // precomputed attn logits [b][i][h][n]
__device__ float g_vt [(size_t)B_ * E_ * N_];    // v transposed [b][d][n]
__device__ float g_bdot[B_ * N_];
__device__ float g_ge [B_ * E_];
__device__ float g_qf [B_ * E_];

// ---------------- graph_emb = mean over nodes ----------------
__global__ void mean_k(const float* __restrict__ ne) {
    int b = blockIdx.x, e = threadIdx.x;
    const float* p = ne + (size_t)b * N_ * E_ + e;
    float s = 0.f;
#pragma unroll 8
    for (int n = 0; n < N_; n++) s += p[(size_t)n * E_];
    g_ge[b * E_ + e] = s * (1.0f / N_);
}

// ---------------- q_first = ge@Wfix + first@Wstep_top + bfix + bstep ----------------
__global__ void qfirst_k(const float* __restrict__ ne,
                         const float* __restrict__ Wfix, const float* __restrict__ bfix,
                         const float* __restrict__ Wstep, const float* __restrict__ bstep) {
    __shared__ float ge_s[E_], fi_s[E_];
    int b = blockIdx.x, t = threadIdx.x;
    ge_s[t] = g_ge[b * E_ + t];
    fi_s[t] = ne[(size_t)b * N_ * E_ + t];
    __syncthreads();
    float acc = bfix[t] + bstep[t];
#pragma unroll 4
    for (int f = 0; f < E_; f++) {
        acc = fmaf(ge_s[f], Wfix[f * E_ + t], acc);
        acc = fmaf(fi_s[f], Wstep[f * E_ + t], acc);
    }
    g_qf[b * E_ + t] = acc;
}

// ---------------- generic fp32 GEMM: C = A(MxK)*B(KxN) [+bias], FFMA2 core ----------------
template <int TRANSB>
__global__ void __launch_bounds__(256) sgemm_k(
    const float* __restrict__ A, const float* __restrict__ Bm,
    const float* __restrict__ bias, float* __restrict__ C,
    int K, int lda, int ldb, int ldc) {
    __shared__ __align__(16) float As[8][128];
    __shared__ __align__(16) float Bs[8][128];
    int tid = threadIdx.x;
    int tx = tid & 15, ty = tid >> 4;
    int rowBase = blockIdx.y * 128;
    int colBase = blockIdx.x * 128;

    u64 acc2[8][4];
#pragma unroll
    for (int i = 0; i < 8; i++)
#pragma unroll
        for (int j = 0; j < 4; j++) acc2[i][j] = 0ULL;

    int aR = tid >> 1;
    int aC = (tid & 1) * 4;
    int bK_n = tid >> 5;
    int bC_n = (tid & 31) * 4;
    int bCol_t = tid & 127;
    int bK_t = (tid >> 7) * 4;

    for (int kt = 0; kt < K; kt += 8) {
        float4 av = *(const float4*)(A + (size_t)(rowBase + aR) * lda + kt + aC);
        As[aC + 0][aR] = av.x; As[aC + 1][aR] = av.y;
        As[aC + 2][aR] = av.z; As[aC + 3][aR] = av.w;
        if (!TRANSB) {
            float4 bv = *(const float4*)(Bm + (size_t)(kt + bK_n) * ldb + colBase + bC_n);
            *(float4*)&Bs[bK_n][bC_n] = bv;
        } else {
            float4 bv = *(const float4*)(Bm + (size_t)(colBase + bCol_t) * ldb + kt + bK_t);
            Bs[bK_t + 0][bCol_t] = bv.x; Bs[bK_t + 1][bCol_t] = bv.y;
            Bs[bK_t + 2][bCol_t] = bv.z; Bs[bK_t + 3][bCol_t] = bv.w;
        }
        __syncthreads();
#pragma unroll
        for (int kk = 0; kk < 8; kk++) {
            float ra[8];
            u64 rb2[4];
            *(float4*)&ra[0] = *(const float4*)&As[kk][ty * 8];
            *(float4*)&ra[4] = *(const float4*)&As[kk][ty * 8 + 4];
            {
                ulonglong2 t0 = *(const ulonglong2*)&Bs[kk][tx * 8];
                ulonglong2 t1 = *(const ulonglong2*)&Bs[kk][tx * 8 + 4];
                rb2[0] = t0.x; rb2[1] = t0.y; rb2[2] = t1.x; rb2[3] = t1.y;
            }
#pragma unroll
            for (int i = 0; i < 8; i++) {
                u64 raa = pack2(ra[i], ra[i]);
#pragma unroll
                for (int j = 0; j < 4; j++) ffma2(acc2[i][j], raa, rb2[j]);
            }
        }
        __syncthreads();
    }
#pragma unroll
    for (int i = 0; i < 8; i++) {
        int r = rowBase + ty * 8 + i;
#pragma unroll
        for (int j = 0; j < 2; j++) {
            int c = colBase + tx * 8 + j * 4;
            float2 p0 = unpack2(acc2[i][2 * j + 0]);
            float2 p1 = unpack2(acc2[i][2 * j + 1]);
            float4 v;
            v.x = p0.x; v.y = p0.y; v.z = p1.x; v.w = p1.y;
            if (bias) { v.x += bias[c]; v.y += bias[c + 1]; v.z += bias[c + 2]; v.w += bias[c + 3]; }
            *(float4*)(C + (size_t)r * ldc + c) = v;
        }
    }
}

// ---------------- P[b][i][h][n] = SCALE * (qf[b]+Qc[b][i])_h . k[b][n]_h ----------------
__global__ void __launch_bounds__(256) pmat_k(float* __restrict__ P) {
    __shared__ __align__(16) float kt[32][132];
    __shared__ __align__(16) float qt[32][132];
    int h = blockIdx.x & 7, b = blockIdx.x >> 3;
    int tid = threadIdx.x;
    const float* kb  = g_qkv + (size_t)b * N_ * 768 + h * 32;
    const float* qcb = g_Qc  + (size_t)b * N_ * 256 + h * 32;
    const float* qfb = g_qf  + b * 256 + h * 32;

    for (int idx = tid; idx < N_ * 8; idx += 256) {
        int n = idx >> 3, d4 = (idx & 7) * 4;
        float4 kv  = *(const float4*)(kb  + (size_t)n * 768 + d4);
        float4 qv  = *(const float4*)(qcb + (size_t)n * 256 + d4);
        float4 qf4 = *(const float4*)(qfb + d4);
        kt[d4 + 0][n] = kv.x; kt[d4 + 1][n] = kv.y;
        kt[d4 + 2][n] = kv.z; kt[d4 + 3][n] = kv.w;
        qt[d4 + 0][n] = qv.x + qf4.x; qt[d4 + 1][n] = qv.y + qf4.y;
        qt[d4 + 2][n] = qv.z + qf4.z; qt[d4 + 3][n] = qv.w + qf4.w;
    }
    __syncthreads();

    int tx = tid & 15, ty = tid >> 4;
    u64 acc2[8][4];
#pragma unroll
    for (int i = 0; i < 8; i++)
#pragma unroll
        for (int j = 0; j < 4; j++) acc2[i][j] = 0ULL;

#pragma unroll 4
    for (int d = 0; d < 32; d++) {
        float ra[8];
        u64 rb2[4];
        *(float4*)&ra[0] = *(const float4*)&qt[d][ty * 8];
        *(float4*)&ra[4] = *(const float4*)&qt[d][ty * 8 + 4];
        {
            ulonglong2 t0 = *(const ulonglong2*)&kt[d][tx * 8];
            ulonglong2 t1 = *(const ulonglong2*)&kt[d][tx * 8 + 4];
            rb2[0] = t0.x; rb2[1] = t0.y; rb2[2] = t1.x; rb2[3] = t1.y;
        }
#pragma unroll
        for (int i = 0; i < 8; i++) {
            u64 raa = pack2(ra[i], ra[i]);
#pragma unroll
            for (int j = 0; j < 4; j++) ffma2(acc2[i][j], raa, rb2[j]);
        }
    }

#pragma unroll
    for (int i = 0; i < 8; i++) {
        float* row = P + ((size_t)(b * N_ + ty * 8 + i)) * 1024 + h * 128 + tx * 8;
#pragma unroll
        for (int j = 0; j < 2; j++) {
            float2 p0 = unpack2(acc2[i][2 * j + 0]);
            float2 p1 = unpack2(acc2[i][2 * j + 1]);
            float4 v;
            v.x = p0.x * SCALE_; v.y = p0.y * SCALE_;
            v.z = p1.x * SCALE_; v.w = p1.y * SCALE_;
            *(float4*)(row + j * 4) = v;
        }
    }
}

// ---------------- v transpose: g_vt[b][d][n] = qkv[b][n][256+d] ----------------
__global__ void __launch_bounds__(256) vtrans_k() {
    __shared__ float ts[32][33];
    int b = blockIdx.x >> 3, dt = blockIdx.x & 7;
    int tid = threadIdx.x;
    const float* src = g_qkv + (size_t)b * N_ * 768 + 256 + dt * 32;
    float* dst = g_vt + ((size_t)b * 256 + dt * 32) * 128;
    for (int nt = 0; nt < 4; nt++) {
        int nn = tid >> 3, dd4 = (tid & 7) * 4;
        float4 vv = *(const float4*)(src + (size_t)(nt * 32 + nn) * 768 + dd4);
        ts[dd4 + 0][nn] = vv.x; ts[dd4 + 1][nn] = vv.y;
        ts[dd4 + 2][nn] = vv.z; ts[dd4 + 3][nn] = vv.w;
        __syncthreads();
        int dd = tid >> 5, n2 = tid & 31;
#pragma unroll
        for (int r = 0; r < 4; r++)
            dst[(size_t)(dd + r * 8) * 128 + nt * 32 + n2] = ts[dd + r * 8][n2];
        __syncthreads();
    }
}

// ---------------- bdot[row] = SCALE * (bmlp . logit_k[row]) ----------------
__global__ void bdot_k(const float* __restrict__ bmlp) {
    int w = threadIdx.x >> 5, l = threadIdx.x & 31;
    int row = blockIdx.x * 8 + w;
    const float* lk = g_qkv + (size_t)row * 768 + 512;
    float acc = 0.f;
#pragma unroll
    for (int j = 0; j < 8; j++) acc = fmaf(bmlp[l + 32 * j], lk[l + 32 * j], acc);
#pragma unroll
    for (int o = 16; o; o >>= 1) acc += __shfl_xor_sync(0xffffffffu, acc, o);
    if (l == 0) g_bdot[row] = acc * SCALE_;
}

// ---------------- sequential greedy decode: 1 CTA (512 thr) per batch ----------------
// R10 structure; B and C inner loops use packed fma.rn.f32x2 (identical numerics:
// the packed lanes map exactly onto the previous dual/quad accumulators).
__global__ void __launch_bounds__(512, 1) decode_k(float* __restrict__ out) {
    extern __shared__ __align__(16) float dyn_s[];
    float4* Ms4T = (float4*)dyn_s;                   // [64 u][MTU], n contiguous

    __shared__ __align__(16) float attn_s[H_ * 132]; // [h][n], +4 pad at n>=64
    __shared__ __align__(16) float ctx_s[E_];
    __shared__ float lp_part[4][N_];
    __shared__ float logits_s[N_];
    __shared__ float bd_s[N_];

    int b = blockIdx.x, tid = threadIdx.x;
    int w = tid >> 5, l = tid & 31;
    int nL = tid & 127, pL = tid >> 7;

    const float4* Mb4 = (const float4*)(g_M + (size_t)b * N_ * E_);
    const float4* Pb = (const float4*)(g_P + (size_t)b * N_ * 1024);

    // ---- stage M transposed: Ms4T[u][n] = M[n][u] ----
    for (int idx = tid; idx < N_ * 64; idx += 512) {
        int n = idx >> 6, u = idx & 63;
        Ms4T[u * MTU + n] = Mb4[n * 64 + u];
    }
    // ---- register cache: first MRC float4 of this thread's M slice (as pairs) ----
    u64 Mreg2[2 * MRC];
#pragma unroll
    for (int i = 0; i < MRC; i++) {
        ulonglong2 t = *(const ulonglong2*)(Mb4 + nL * 64 + pL * 16 + i);
        Mreg2[2 * i] = t.x; Mreg2[2 * i + 1] = t.y;
    }

    // ---- stage v into regs as packed pairs: thread t holds v[nh*64+i][d] ----
    u64 v2[32];
    {
        int d = tid >> 1, nh = tid & 1;
        const ulonglong2* vb2 = (const ulonglong2*)(g_vt + ((size_t)b * 256 + d) * 128 + nh * 64);
#pragma unroll
        for (int i = 0; i < 16; i++) {
            ulonglong2 t = vb2[i];
            v2[2 * i] = t.x; v2[2 * i + 1] = t.y;
        }
    }
    if (tid < N_) bd_s[tid] = g_bdot[b * N_ + tid];
    __syncthreads();

    // register state (redundant per thread)
    unsigned visA = (l == 0) ? 1u : 0u;              // bits 0..3 for n = 4l..4l+3
    unsigned visD = (l == 0) ? 1u : 0u;              // bit j for n = l + 32j
    float lp = 0.f;

    // prime: P row for cur = 0
    float4 pv;
    if (w < 8) pv = Pb[0 * 256 + w * 32 + l];

    for (int step = 0; step < N_ - 1; step++) {
        // ---- A: warps 0..7 = heads; lane l owns n = 4l..4l+3 ----
        if (w < 8) {
            int n0 = 4 * l;
            float a0 = (visA & 1u) ? NEGV : pv.x;
            float a1 = (visA & 2u) ? NEGV : pv.y;
            float a2 = (visA & 4u) ? NEGV : pv.z;
            float a3 = (visA & 8u) ? NEGV : pv.w;
            float m = fmaxf(fmaxf(a0, a1), fmaxf(a2, a3));
#pragma unroll
            for (int o = 16; o; o >>= 1) m = fmaxf(m, __shfl_xor_sync(0xffffffffu, m, o));
            a0 = expf(a0 - m); a1 = expf(a1 - m); a2 = expf(a2 - m); a3 = expf(a3 - m);
            float ssum = a0 + a1 + a2 + a3;
#pragma unroll
            for (int o = 16; o; o >>= 1) ssum += __shfl_xor_sync(0xffffffffu, ssum, o);
            float inv = 1.0f / ssum;
            float4 wv;
            wv.x = a0 * inv; wv.y = a1 * inv; wv.z = a2 * inv; wv.w = a3 * inv;
            *(float4*)&attn_s[w * 132 + n0 + 4 * (l >= 16)] = wv;
        }
        __syncthreads();

        // ---- B: ctx[d] = sum_n attn[h(d)][n] * v[n][d]  (packed FFMA2) ----
        {
            int d = tid >> 1, nh = tid & 1, hh = d >> 5;
            const ulonglong2* ap2 = (const ulonglong2*)(attn_s + hh * 132 + nh * 68);
            u64 acc2 = 0ULL;
#pragma unroll
            for (int i = 0; i < 16; i++) {
                ulonglong2 av = ap2[i];
                ffma2(acc2, av.x, v2[2 * i]);
                ffma2(acc2, av.y, v2[2 * i + 1]);
            }
            float2 ac = unpack2(acc2);
            float acc = ac.x + ac.y;
            acc += __shfl_xor_sync(0xffffffffu, acc, 1);
            if (!nh) ctx_s[d] = acc;
        }
        __syncthreads();

        // ---- C: logits partials (packed FFMA2; first MRC float4 from regs) ----
        {
            const ulonglong2* c2 = (const ulonglong2*)ctx_s + pL * 16;
            const ulonglong2* mr = (const ulonglong2*)Ms4T + (pL * 16) * MTU + nL;
            u64 sA = 0ULL, sB = 0ULL;
#pragma unroll
            for (int i = 0; i < MRC; i++) {
                ulonglong2 c = c2[i];
                ffma2(sA, Mreg2[2 * i], c.x);
                ffma2(sB, Mreg2[2 * i + 1], c.y);
            }
#pragma unroll
            for (int i = MRC; i < 16; i++) {
                ulonglong2 mv = mr[i * MTU];
                ulonglong2 c = c2[i];
                ffma2(sA, mv.x, c.x);
                ffma2(sB, mv.y, c.y);
            }
            float2 a = unpack2(sA), bq = unpack2(sB);
            lp_part[pL][nL] = (a.x + a.y) + (bq.x + bq.y);
        }
        __syncthreads();

        // ---- D: tid<128 (n = tid): sum partials, one tanhf, mask -> logits_s ----
        if (tid < N_) {
            float s = lp_part[0][tid] + lp_part[1][tid] + lp_part[2][tid] + lp_part[3][tid];
            float lg = tanhf(fmaf(SCALE_, s, bd_s[tid])) * CLIPV;
            if ((visD >> w) & 1u) lg = NEGV;         // w<4, n = 32w + l, visD bit w
            logits_s[tid] = lg;
        }
        __syncthreads();

        // ---- E: argmax -> state -> issue next load -> lse behind the load ----
        {
            float lv[4];
            float bv = -3.0e38f; int bi = 0;
#pragma unroll
            for (int j = 0; j < 4; j++) {
                lv[j] = logits_s[l + 32 * j];
                if (lv[j] > bv) { bv = lv[j]; bi = l + 32 * j; }
            }
#pragma unroll
            for (int o = 16; o; o >>= 1) {
                float ov = __shfl_xor_sync(0xffffffffu, bv, o);
                int oi = __shfl_xor_sync(0xffffffffu, bi, o);
                if (ov > bv || (ov == bv && oi < bi)) { bv = ov; bi = oi; }
            }
            // state update + immediately issue next P row load
            if ((bi >> 2) == l) visA |= 1u << (bi & 3);
            if ((bi & 31) == l) visD |= 1u << (bi >> 5);
            if (w < 8) pv = Pb[(size_t)bi * 256 + w * 32 + l];

            // lse + logp while the load is in flight
            float es = 0.f;
#pragma unroll
            for (int j = 0; j < 4; j++) es += expf(lv[j] - bv);
#pragma unroll
            for (int o = 16; o; o >>= 1) es += __shfl_xor_sync(0xffffffffu, es, o);
            lp -= logf(es);
        }
        // no trailing barrier: bar1..bar4 of the next step order all smem reuse
    }

    if (tid == 0) out[b] = lp;
}

// ---------------- host launch ----------------
extern "C" void kernel_launch(void* const* d_in, const int* in_sizes, int n_in,
                              void* d_out, int out_size) {
    const float* ne    = (const float*)d_in[0];
    const float* Wqkv  = (const float*)d_in[1];
    const float* bqkv  = (const float*)d_in[2];
    const float* Wfix  = (const float*)d_in[3];
    const float* bfix  = (const float*)d_in[4];
    const float* Wstep = (const float*)d_in[5];
    const float* bstep = (const float*)d_in[6];
    const float* Wmlp  = (const float*)d_in[7];
    const float* bmlp  = (const float*)d_in[8];
    float* out = (float*)d_out;

    float *p_qkv = nullptr, *p_Qc = nullptr, *p_M = nullptr, *p_P = nullptr;
    cudaGetSymbolAddress((void**)&p_qkv, g_qkv);
    cudaGetSymbolAddress((void**)&p_Qc, g_Qc);
    cudaGetSymbolAddress((void**)&p_M, g_M);
    cudaGetSymbolAddress((void**)&p_P, g_P);

    size_t dec_smem = (size_t)64 * MTU * sizeof(float4);   // 132096
    cudaFuncSetAttribute(decode_k, cudaFuncAttributeMaxDynamicSharedMemorySize,
                         (int)dec_smem);

    mean_k<<<B_, E_>>>(ne);
    qfirst_k<<<B_, E_>>>(ne, Wfix, bfix, Wstep, bstep);

    sgemm_k<0><<<dim3(768 / 128, (B_ * N_) / 128), 256>>>(ne, Wqkv, bqkv, p_qkv,
                                                          E_, E_, 768, 768);
    sgemm_k<0><<<dim3(E_ / 128, (B_ * N_) / 128), 256>>>(ne, Wstep + 256 * 256, nullptr,
                                                         p_Qc, E_, E_, E_, E_);
    sgemm_k<1><<<dim3(E_ / 128, (B_ * N_) / 128), 256>>>(p_qkv + 512, Wmlp, nullptr,
                                                         p_M, E_, 768, E_, E_);
    pmat_k<<<B_ * H_, 256>>>(p_P);
    vtrans_k<<<B_ * 8, 256>>>();
    bdot_k<<<(B_ * N_) / 8, 256>>>(bmlp);

    decode_k<<<B_, 512, dec_smem>>>(out);
}